// round 4
// baseline (speedup 1.0000x reference)
#include <cuda_runtime.h>
#include <cstdint>

static constexpr int K_TOTAL = 1280, N_TOTAL = 1280;
static constexpr int BM = 128, BN = 128;
static constexpr int SLICES = 40;               // K / 32
static constexpr int NTILES = 10, MTILES = 512;
static constexpr int GRID = NTILES * MTILES;    // 5120
static constexpr int THREADS = 256;

// smem byte offsets (double buffered)
static constexpr int A_ST = 16384, B_ST = 16384, B2_ST = 1024;
static constexpr int OFF_A = 0;          // 2 * 16KB
static constexpr int OFF_B = 32768;      // 2 * 16KB
static constexpr int OFF_B2 = 65536;     // 2 * 1KB
static constexpr int OFF_WU = 67584;     // 2KB
static constexpr int OFF_DN = 69632;     // 2KB
static constexpr int SMEM_BYTES = 71680;

// W in fragment order: [ntile][slice][wc(4)][nf(4)][ks(4)][lane(32)][2]
__device__ __align__(16) float g_Wfrag[NTILES * SLICES * 4096];
// Wd in fragment order: [lora][slice][ks][lane][2] (n-cols 4..7 zero)
__device__ __align__(16) float g_Wdfrag[50 * SLICES * 256];

__device__ __forceinline__ uint32_t smem_u32(const void* p) {
    uint32_t a;
    asm("{ .reg .u64 t; cvta.to.shared.u64 t, %1; cvt.u32.u64 %0, t; }" : "=r"(a) : "l"(p));
    return a;
}
__device__ __forceinline__ uint32_t rna(float f) {
    uint32_t b;
    asm("cvt.rna.tf32.f32 %0, %1;" : "=r"(b) : "f"(f));
    return b;
}
__device__ __forceinline__ void mma8(float* c, const uint32_t* a, const uint32_t* b) {
    asm volatile(
        "mma.sync.aligned.m16n8k8.row.col.f32.tf32.tf32.f32 "
        "{%0,%1,%2,%3}, {%4,%5,%6,%7}, {%8,%9}, {%0,%1,%2,%3};"
        : "+f"(c[0]), "+f"(c[1]), "+f"(c[2]), "+f"(c[3])
        : "r"(a[0]), "r"(a[1]), "r"(a[2]), "r"(a[3]), "r"(b[0]), "r"(b[1]));
}
#define CP16(d, s) asm volatile("cp.async.cg.shared.global [%0], [%1], 16;" :: "r"(d), "l"(s))
#define CP4(d, s)  asm volatile("cp.async.ca.shared.global [%0], [%1], 4;"  :: "r"(d), "l"(s))
#define CP_COMMIT() asm volatile("cp.async.commit_group;")
#define CP_WAIT0()  asm volatile("cp.async.wait_group 0;" ::: "memory")

// ---------------- prepass: rna-round W/Wd, scatter into fragment layout
__global__ void prep_kernel(const float* __restrict__ W, const float* __restrict__ Wd) {
    int i = blockIdx.x * blockDim.x + threadIdx.x;
    const int NW = N_TOTAL * K_TOTAL;
    if (i < NW) {
        int n = i / K_TOTAL, k = i % K_TOTAL;
        int ntile = n >> 7, nn = n & 127, wc = nn >> 5, nf = (nn >> 3) & 3, gid = nn & 7;
        int slice = k >> 5, ks = (k >> 3) & 3, kh = (k >> 2) & 1, tig = k & 3;
        int off = (ntile * SLICES + slice) * 4096 +
                  (((wc * 4 + nf) * 4 + ks) * 32 + gid * 4 + tig) * 2 + kh;
        g_Wfrag[off] = __uint_as_float(rna(W[i]));
    } else if (i < NW + 50 * K_TOTAL * 8) {
        int j = i - NW;
        int gid = j & 7, t = j >> 3, k = t % K_TOTAL, l = t / K_TOTAL;
        float v = 0.f;
        if (gid < 4) v = __uint_as_float(rna(Wd[(l * 4 + gid) * K_TOTAL + k]));
        int slice = k >> 5, ks = (k >> 3) & 3, kh = (k >> 2) & 1, tig = k & 3;
        g_Wdfrag[(l * SLICES + slice) * 256 + (ks * 32 + gid * 4 + tig) * 2 + kh] = v;
    }
}

// ---------------- main fused kernel
__global__ void __launch_bounds__(THREADS, 2)
lora_gemm(const float* __restrict__ x, const int* __restrict__ lora_id,
          const float* __restrict__ Wu, float* __restrict__ out) {
    extern __shared__ char smem[];
    const uint32_t sb = smem_u32(smem);
    const int tid = threadIdx.x, lane = tid & 31, wid = tid >> 5;
    const int bid = blockIdx.x;
    const int ntile = bid % NTILES, mtile = bid / NTILES;
    const int m0 = mtile * BM, nb = ntile * BN;

    const int id = lora_id[m0 >> 12];
    const int idx = (id >= 0) ? ((id >> 2) > 49 ? 49 : (id >> 2)) : 0;
    const float coeff = (id >= 0) ? 1.f : 0.f;

    // stage Wu tile (full fp32): 128 float4
    if (tid < 128) {
        const float4* wusrc = (const float4*)Wu + (size_t)idx * N_TOTAL + nb;
        ((float4*)(smem + OFF_WU))[tid] = wusrc[tid];
    }

    const int gid = lane >> 2, tig = lane & 3;
    const int wr = wid >> 2, wc = wid & 3;

    // producer indexing (A): thread -> (row, k-half)
    const int pr = tid >> 1, pq = tid & 1;
    const float* xrow = x + (size_t)(m0 + pr) * K_TOTAL + pq * 16;
    const int awr = pr >> 6, amf = (pr >> 4) & 3, agid = pr & 7, ah = (pr >> 3) & 1;

    const float* wsrc = g_Wfrag + (size_t)ntile * SLICES * 4096;
    const float* wdsrc = g_Wdfrag + (size_t)idx * SLICES * 256;

    float acc[4][4][4];
    float accL[4][4];
    #pragma unroll
    for (int a = 0; a < 4; ++a) {
        #pragma unroll
        for (int b = 0; b < 4; ++b)
            acc[a][b][0] = acc[a][b][1] = acc[a][b][2] = acc[a][b][3] = 0.f;
        accL[a][0] = accL[a][1] = accL[a][2] = accL[a][3] = 0.f;
    }

    // ---- preload slice 0 into stage 0
    {
        CP4(sb + OFF_B2 + tid * 4, wdsrc + tid);
        #pragma unroll
        for (int c = 0; c < 4; ++c)
            CP16(sb + OFF_B + tid * 64 + c * 16, wsrc + tid * 16 + c * 4);
        CP_COMMIT();
        #pragma unroll
        for (int j = 0; j < 4; ++j) {
            float4 v = ((const float4*)xrow)[j];
            int q = pq * 4 + j, ksj = q >> 1, khj = q & 1;
            float* ap = (float*)(smem + OFF_A) +
                        ((((awr * 4 + amf) * 4 + ksj) * 32 + agid * 4) * 16 +
                         (ah + 2 * khj) * 4) / 4;
            ap[0] = __uint_as_float(rna(v.x));
            ap[4] = __uint_as_float(rna(v.y));
            ap[8] = __uint_as_float(rna(v.z));
            ap[12] = __uint_as_float(rna(v.w));
        }
        CP_WAIT0();
        __syncthreads();
    }

    // ---- main loop
    #pragma unroll 1
    for (int s = 0; s < SLICES; ++s) {
        const int cur = s & 1, nxt = cur ^ 1;
        const bool pf = (s + 1) < SLICES;
        float4 av[4];
        if (pf) {
            const float* xp = xrow + (s + 1) * 32;
            #pragma unroll
            for (int j = 0; j < 4; ++j) av[j] = ((const float4*)xp)[j];
            const float* wp = wsrc + (size_t)(s + 1) * 4096;
            CP4(sb + OFF_B2 + nxt * B2_ST + tid * 4, wdsrc + (s + 1) * 256 + tid);
            #pragma unroll
            for (int c = 0; c < 4; ++c)
                CP16(sb + OFF_B + nxt * B_ST + tid * 64 + c * 16, wp + tid * 16 + c * 4);
            CP_COMMIT();
        }
        // compute on cur
        const uint32_t abase = sb + OFF_A + cur * A_ST + ((wr * 16) * 32 + lane) * 16;
        const uint32_t bbase = sb + OFF_B + cur * B_ST + ((wc * 16) * 32 + lane) * 8;
        const uint32_t b2base = sb + OFF_B2 + cur * B2_ST + lane * 8;
        #pragma unroll
        for (int ks = 0; ks < 4; ++ks) {
            uint32_t a[4][4];
            #pragma unroll
            for (int mf = 0; mf < 4; ++mf)
                asm volatile("ld.shared.v4.b32 {%0,%1,%2,%3}, [%4];"
                             : "=r"(a[mf][0]), "=r"(a[mf][1]), "=r"(a[mf][2]), "=r"(a[mf][3])
                             : "r"(abase + ((mf * 4 + ks) * 32) * 16));
            #pragma unroll
            for (int nf = 0; nf < 4; ++nf) {
                uint32_t b[2];
                asm volatile("ld.shared.v2.b32 {%0,%1}, [%2];"
                             : "=r"(b[0]), "=r"(b[1])
                             : "r"(bbase + ((nf * 4 + ks) * 32) * 8));
                #pragma unroll
                for (int mf = 0; mf < 4; ++mf) mma8(acc[mf][nf], a[mf], b);
            }
            if (wc == 0) {
                uint32_t b2[2];
                asm volatile("ld.shared.v2.b32 {%0,%1}, [%2];"
                             : "=r"(b2[0]), "=r"(b2[1]) : "r"(b2base + (ks * 32) * 8));
                #pragma unroll
                for (int mf = 0; mf < 4; ++mf) mma8(accL[mf], a[mf], b2);
            }
        }
        if (pf) {
            float* ast = (float*)(smem + OFF_A + nxt * A_ST);
            #pragma unroll
            for (int j = 0; j < 4; ++j) {
                int q = pq * 4 + j, ksj = q >> 1, khj = q & 1;
                float* ap = ast + ((((awr * 4 + amf) * 4 + ksj) * 32 + agid * 4) * 16 +
                                   (ah + 2 * khj) * 4) / 4;
                ap[0] = __uint_as_float(rna(av[j].x));
                ap[4] = __uint_as_float(rna(av[j].y));
                ap[8] = __uint_as_float(rna(av[j].z));
                ap[12] = __uint_as_float(rna(av[j].w));
            }
        }
        CP_WAIT0();
        __syncthreads();
    }

    // ---- epilogue: stage lora-down, then fused add + store
    float* dns = (float*)(smem + OFF_DN);
    if (wc == 0 && tig < 2) {
        #pragma unroll
        for (int mf = 0; mf < 4; ++mf) {
            int mlo = wr * 64 + mf * 16 + gid, mhi = mlo + 8;
            dns[mlo * 4 + 2 * tig] = accL[mf][0] * coeff;
            dns[mlo * 4 + 2 * tig + 1] = accL[mf][1] * coeff;
            dns[mhi * 4 + 2 * tig] = accL[mf][2] * coeff;
            dns[mhi * 4 + 2 * tig + 1] = accL[mf][3] * coeff;
        }
    }
    __syncthreads();

    const float4* wus = (const float4*)(smem + OFF_WU);
    #pragma unroll
    for (int mf = 0; mf < 4; ++mf) {
        int mlo = wr * 64 + mf * 16 + gid, mhi = mlo + 8;
        float4 dlo = ((const float4*)dns)[mlo];
        float4 dhi = ((const float4*)dns)[mhi];
        float* olo = out + (size_t)(m0 + mlo) * N_TOTAL + nb;
        float* ohi = out + (size_t)(m0 + mhi) * N_TOTAL + nb;
        #pragma unroll
        for (int nf = 0; nf < 4; ++nf) {
            int n = wc * 32 + nf * 8 + 2 * tig;
            float4 w0 = wus[n], w1 = wus[n + 1];
            float2 vlo, vhi;
            vlo.x = acc[mf][nf][0] + dlo.x * w0.x + dlo.y * w0.y + dlo.z * w0.z + dlo.w * w0.w;
            vlo.y = acc[mf][nf][1] + dlo.x * w1.x + dlo.y * w1.y + dlo.z * w1.z + dlo.w * w1.w;
            vhi.x = acc[mf][nf][2] + dhi.x * w0.x + dhi.y * w0.y + dhi.z * w0.z + dhi.w * w0.w;
            vhi.y = acc[mf][nf][3] + dhi.x * w1.x + dhi.y * w1.y + dhi.z * w1.z + dhi.w * w1.w;
            *(float2*)(olo + n) = vlo;
            *(float2*)(ohi + n) = vhi;
        }
    }
}

extern "C" void kernel_launch(void* const* d_in, const int* in_sizes, int n_in,
                              void* d_out, int out_size) {
    const float* x = (const float*)d_in[0];
    const int* lid = (const int*)d_in[1];
    const float* W = (const float*)d_in[2];
    const float* Wd = (const float*)d_in[3];
    const float* Wu = (const float*)d_in[4];
    float* out = (float*)d_out;

    cudaFuncSetAttribute(lora_gemm, cudaFuncAttributeMaxDynamicSharedMemorySize, SMEM_BYTES);
    int total = N_TOTAL * K_TOTAL + 50 * K_TOTAL * 8;
    prep_kernel<<<(total + 255) / 256, 256>>>(W, Wd);
    lora_gemm<<<GRID, THREADS, SMEM_BYTES>>>(x, lid, Wu, out);
}

// round 6
// speedup vs baseline: 1.1188x; 1.1188x over previous
#include <cuda_runtime.h>
#include <cstdint>

static constexpr int K_TOTAL = 1280, N_TOTAL = 1280;
static constexpr int BM = 128, BN = 256;
static constexpr int SLICES32 = 40, SLICES64 = 20;
static constexpr int NTILES = 5, MTILES = 512;
static constexpr int GRID = NTILES * MTILES;  // 2560
static constexpr int THREADS = 256;

// smem (bytes): A 2*32K | B 2*64K | B2 2*2K | WU 4K | DN 2K
static constexpr int A_ST = 32768, B_ST = 65536, B2_ST = 2048;
static constexpr int OFF_A = 0;
static constexpr int OFF_B = 65536;
static constexpr int OFF_B2 = 196608;
static constexpr int OFF_WU = 200704;
static constexpr int OFF_DN = 204800;
static constexpr int SMEM_BYTES = 206848;

// W fragments, per 32-k slice block of 8192 floats:
// ((((wc*4+nfp)*4+ks)*32 + gid*4 + tig)*4 + nfo*2 + kh)
__device__ __align__(16) float g_Wfrag[NTILES * SLICES32 * 8192];
// Wd fragments: [lora][slice32][(ks*32+lane)*2 + kh]
__device__ __align__(16) float g_Wdfrag[50 * SLICES32 * 256];

__device__ __forceinline__ uint32_t smem_u32(const void* p) {
    uint32_t a;
    asm("{ .reg .u64 t; cvta.to.shared.u64 t, %1; cvt.u32.u64 %0, t; }" : "=r"(a) : "l"(p));
    return a;
}
__device__ __forceinline__ uint32_t rna(float f) {
    uint32_t b;
    asm("cvt.rna.tf32.f32 %0, %1;" : "=r"(b) : "f"(f));
    return b;
}
__device__ __forceinline__ void mma8(float* c, const uint32_t* a, uint32_t b0, uint32_t b1) {
    asm volatile(
        "mma.sync.aligned.m16n8k8.row.col.f32.tf32.tf32.f32 "
        "{%0,%1,%2,%3}, {%4,%5,%6,%7}, {%8,%9}, {%0,%1,%2,%3};"
        : "+f"(c[0]), "+f"(c[1]), "+f"(c[2]), "+f"(c[3])
        : "r"(a[0]), "r"(a[1]), "r"(a[2]), "r"(a[3]), "r"(b0), "r"(b1));
}
#define CP16(d, s) asm volatile("cp.async.cg.shared.global [%0], [%1], 16;" :: "r"(d), "l"(s))
#define CP8(d, s)  asm volatile("cp.async.ca.shared.global [%0], [%1], 8;"  :: "r"(d), "l"(s))
#define CP_COMMIT() asm volatile("cp.async.commit_group;")
#define CP_WAIT0()  asm volatile("cp.async.wait_group 0;" ::: "memory")

// ---------------- prepass
__global__ void prep_kernel(const float* __restrict__ W, const float* __restrict__ Wd) {
    int i = blockIdx.x * blockDim.x + threadIdx.x;
    const int NW = N_TOTAL * K_TOTAL;
    if (i < NW) {
        int n = i / K_TOTAL, k = i % K_TOTAL;
        int ntile = n >> 8, nn = n & 255;
        int wc = nn >> 6, nf = (nn >> 3) & 7, gid = nn & 7;
        int nfp = nf >> 1, nfo = nf & 1;
        int slice = k >> 5, ks = (k >> 3) & 3, kh = (k >> 2) & 1, tig = k & 3;
        int off = (ntile * SLICES32 + slice) * 8192 +
                  ((((wc * 4 + nfp) * 4 + ks) * 32 + gid * 4 + tig) * 4 + nfo * 2 + kh);
        g_Wfrag[off] = __uint_as_float(rna(W[i]));
    } else if (i < NW + 50 * K_TOTAL * 8) {
        int j = i - NW;
        int gid = j & 7, t = j >> 3, k = t % K_TOTAL, l = t / K_TOTAL;
        float v = 0.f;
        if (gid < 4) v = __uint_as_float(rna(Wd[(l * 4 + gid) * K_TOTAL + k]));
        int slice = k >> 5, ks = (k >> 3) & 3, kh = (k >> 2) & 1, tig = k & 3;
        g_Wdfrag[(l * SLICES32 + slice) * 256 + (ks * 32 + gid * 4 + tig) * 2 + kh] = v;
    }
}

// ---------------- main fused kernel
__global__ void __launch_bounds__(THREADS, 1)
lora_gemm(const float* __restrict__ x, const int* __restrict__ lora_id,
          const float* __restrict__ Wu, float* __restrict__ out) {
    extern __shared__ char smem[];
    const uint32_t sb = smem_u32(smem);
    const int tid = threadIdx.x, lane = tid & 31, wid = tid >> 5;
    const int bid = blockIdx.x;
    const int ntile = bid % NTILES, mtile = bid / NTILES;
    const int m0 = mtile * BM, nb = ntile * BN;

    const int id = lora_id[m0 >> 12];
    const int idx = (id >= 0) ? ((id >> 2) > 49 ? 49 : (id >> 2)) : 0;
    const float coeff = (id >= 0) ? 1.f : 0.f;

    // stage Wu tile (fp32), 256 float4
    {
        const float4* wusrc = (const float4*)Wu + (size_t)idx * N_TOTAL;
        ((float4*)(smem + OFF_WU))[tid] = wusrc[nb + tid];
    }

    const int gid = lane >> 2, tig = lane & 3;
    const int wr = wid >> 2, wc = wid & 3;

    // producer indexing: row pr, k-half pq (32 floats each)
    const int pr = tid >> 1, pq = tid & 1;
    const float* xrow = x + (size_t)(m0 + pr) * K_TOTAL + pq * 32;
    const int mfgp = pr >> 4, agid = pr & 7, ah = (pr >> 3) & 1;
    const int sA = (agid >> 1) & 3;
    const uint32_t asts = sb + OFF_A + pq * 16384 +
                          ((mfgp * 4 * 32 + agid * 4) << 4) + ah * 4;

    // swizzled consumer bases
    const uint32_t acons = sb + OFF_A + ((wr * 16 * 32) << 4) +
                           ((gid * 4 + (tig ^ ((gid >> 1) & 3))) << 4);
    const uint32_t bcons = sb + OFF_B + wc * 8192 + (lane << 4);
    const uint32_t b2cons = sb + OFF_B2 + lane * 8;

    const float* wsrc = g_Wfrag + (size_t)ntile * SLICES32 * 8192;
    const float* wdsrc = g_Wdfrag + (size_t)idx * SLICES32 * 256;

    float acc[4][8][4];
    float accL[4][4];
    #pragma unroll
    for (int a = 0; a < 4; ++a) {
        #pragma unroll
        for (int b = 0; b < 8; ++b)
            acc[a][b][0] = acc[a][b][1] = acc[a][b][2] = acc[a][b][3] = 0.f;
        accL[a][0] = accL[a][1] = accL[a][2] = accL[a][3] = 0.f;
    }

    // ---- preload slice64 0 into stage 0
    {
        #pragma unroll
        for (int c = 0; c < 16; ++c)
            CP16(sb + OFF_B + tid * 256 + c * 16, wsrc + tid * 64 + c * 4);
        CP8(sb + OFF_B2 + tid * 8, wdsrc + tid * 2);
        CP_COMMIT();
        #pragma unroll
        for (int ph = 0; ph < 2; ++ph) {
            #pragma unroll
            for (int j = 0; j < 4; ++j) {
                float4 v = ((const float4*)(xrow + ph * 16))[j];
                uint32_t r0 = rna(v.x), r1 = rna(v.y), r2 = rna(v.z), r3 = rna(v.w);
                uint32_t ab = asts + (((ph * 2 + (j >> 1)) * 32) << 4) + (j & 1) * 8;
                asm volatile("st.shared.b32 [%0], %1;" :: "r"(ab + ((0 ^ sA) << 4)), "r"(r0));
                asm volatile("st.shared.b32 [%0], %1;" :: "r"(ab + ((1 ^ sA) << 4)), "r"(r1));
                asm volatile("st.shared.b32 [%0], %1;" :: "r"(ab + ((2 ^ sA) << 4)), "r"(r2));
                asm volatile("st.shared.b32 [%0], %1;" :: "r"(ab + ((3 ^ sA) << 4)), "r"(r3));
            }
        }
        CP_WAIT0();
        __syncthreads();
    }

    // ---- main loop over 64-k slices
    #pragma unroll 1
    for (int s = 0; s < SLICES64; ++s) {
        const int cur = s & 1, nxt = cur ^ 1;
        const bool pf = (s + 1) < SLICES64;
        if (pf) {
            const float* wp = wsrc + (size_t)(s + 1) * 16384;
            #pragma unroll
            for (int c = 0; c < 16; ++c)
                CP16(sb + OFF_B + nxt * B_ST + tid * 256 + c * 16, wp + tid * 64 + c * 4);
            CP8(sb + OFF_B2 + nxt * B2_ST + tid * 8, wdsrc + (s + 1) * 512 + tid * 2);
            CP_COMMIT();
        }
        #pragma unroll
        for (int ph = 0; ph < 2; ++ph) {
            float4 xv[4];
            if (pf) {
                const float* xp = xrow + (s + 1) * 64 + ph * 16;
                #pragma unroll
                for (int j = 0; j < 4; ++j) xv[j] = ((const float4*)xp)[j];
            }
            const uint32_t ab0 = acons + cur * A_ST + ph * 16384;
            const uint32_t bb0 = bcons + cur * B_ST + ph * 32768;
            const uint32_t b20 = b2cons + cur * B2_ST + ph * 1024;
            #pragma unroll
            for (int ksl = 0; ksl < 4; ++ksl) {
                uint32_t a[4][4];
                #pragma unroll
                for (int mf = 0; mf < 4; ++mf)
                    asm volatile("ld.shared.v4.b32 {%0,%1,%2,%3}, [%4];"
                                 : "=r"(a[mf][0]), "=r"(a[mf][1]), "=r"(a[mf][2]), "=r"(a[mf][3])
                                 : "r"(ab0 + (((mf * 4 + ksl) * 32) << 4)));
                #pragma unroll
                for (int nfp = 0; nfp < 4; ++nfp) {
                    uint32_t b[4];
                    asm volatile("ld.shared.v4.b32 {%0,%1,%2,%3}, [%4];"
                                 : "=r"(b[0]), "=r"(b[1]), "=r"(b[2]), "=r"(b[3])
                                 : "r"(bb0 + (((nfp * 4 + ksl) * 32) << 4)));
                    #pragma unroll
                    for (int mf = 0; mf < 4; ++mf) {
                        mma8(acc[mf][2 * nfp], a[mf], b[0], b[1]);
                        mma8(acc[mf][2 * nfp + 1], a[mf], b[2], b[3]);
                    }
                }
                if (wc == 0) {
                    uint32_t b2[2];
                    asm volatile("ld.shared.v2.b32 {%0,%1}, [%2];"
                                 : "=r"(b2[0]), "=r"(b2[1]) : "r"(b20 + ksl * 256));
                    #pragma unroll
                    for (int mf = 0; mf < 4; ++mf) mma8(accL[mf], a[mf], b2[0], b2[1]);
                }
            }
            if (pf) {
                #pragma unroll
                for (int j = 0; j < 4; ++j) {
                    uint32_t r0 = rna(xv[j].x), r1 = rna(xv[j].y),
                             r2 = rna(xv[j].z), r3 = rna(xv[j].w);
                    uint32_t ab = asts + nxt * A_ST +
                                  (((ph * 2 + (j >> 1)) * 32) << 4) + (j & 1) * 8;
                    asm volatile("st.shared.b32 [%0], %1;" :: "r"(ab + ((0 ^ sA) << 4)), "r"(r0));
                    asm volatile("st.shared.b32 [%0], %1;" :: "r"(ab + ((1 ^ sA) << 4)), "r"(r1));
                    asm volatile("st.shared.b32 [%0], %1;" :: "r"(ab + ((2 ^ sA) << 4)), "r"(r2));
                    asm volatile("st.shared.b32 [%0], %1;" :: "r"(ab + ((3 ^ sA) << 4)), "r"(r3));
                }
            }
        }
        CP_WAIT0();
        __syncthreads();
    }

    // ---- epilogue: stage lora-down, fused add + store
    float* dns = (float*)(smem + OFF_DN);
    if (wc == 0 && tig < 2) {
        #pragma unroll
        for (int mf = 0; mf < 4; ++mf) {
            int mlo = wr * 64 + mf * 16 + gid, mhi = mlo + 8;
            dns[mlo * 4 + 2 * tig] = accL[mf][0] * coeff;
            dns[mlo * 4 + 2 * tig + 1] = accL[mf][1] * coeff;
            dns[mhi * 4 + 2 * tig] = accL[mf][2] * coeff;
            dns[mhi * 4 + 2 * tig + 1] = accL[mf][3] * coeff;
        }
    }
    __syncthreads();

    const float4* wus = (const float4*)(smem + OFF_WU);
    #pragma unroll
    for (int mf = 0; mf < 4; ++mf) {
        int mlo = wr * 64 + mf * 16 + gid, mhi = mlo + 8;
        float4 dlo = ((const float4*)dns)[mlo];
        float4 dhi = ((const float4*)dns)[mhi];
        float* olo = out + (size_t)(m0 + mlo) * N_TOTAL + nb;
        float* ohi = out + (size_t)(m0 + mhi) * N_TOTAL + nb;
        #pragma unroll
        for (int nf = 0; nf < 8; ++nf) {
            int n = wc * 64 + nf * 8 + 2 * tig;
            float4 w0 = wus[n], w1 = wus[n + 1];
            float2 vlo, vhi;
            vlo.x = acc[mf][nf][0] + dlo.x * w0.x + dlo.y * w0.y + dlo.z * w0.z + dlo.w * w0.w;
            vlo.y = acc[mf][nf][1] + dlo.x * w1.x + dlo.y * w1.y + dlo.z * w1.z + dlo.w * w1.w;
            vhi.x = acc[mf][nf][2] + dhi.x * w0.x + dhi.y * w0.y + dhi.z * w0.z + dhi.w * w0.w;
            vhi.y = acc[mf][nf][3] + dhi.x * w1.x + dhi.y * w1.y + dhi.z * w1.z + dhi.w * w1.w;
            *(float2*)(olo + n) = vlo;
            *(float2*)(ohi + n) = vhi;
        }
    }
}

extern "C" void kernel_launch(void* const* d_in, const int* in_sizes, int n_in,
                              void* d_out, int out_size) {
    const float* x = (const float*)d_in[0];
    const int* lid = (const int*)d_in[1];
    const float* W = (const float*)d_in[2];
    const float* Wd = (const float*)d_in[3];
    const float* Wu = (const float*)d_in[4];
    float* out = (float*)d_out;

    cudaFuncSetAttribute(lora_gemm, cudaFuncAttributeMaxDynamicSharedMemorySize, SMEM_BYTES);
    int total = N_TOTAL * K_TOTAL + 50 * K_TOTAL * 8;
    prep_kernel<<<(total + 255) / 256, 256>>>(W, Wd);
    lora_gemm<<<GRID, THREADS, SMEM_BYTES>>>(x, lid, Wu, out);
}